// round 16
// baseline (speedup 1.0000x reference)
#include <cuda_runtime.h>
#include <math.h>

#define Bn   32
#define Tn   512
#define Mn   2048
#define Ln   1024
#define NMEL 80
#define DSPK 256

#define MEL_BLOCKS  512                  // 16 per batch, 128 mel-rows each
#define ATTN_PER_B  10
#define ATTN_ROWS   52                   // ceil(512/10), last chunk clamped
#define ATTN_BLOCKS (Bn * ATTN_PER_B)    // 320
#define DUR_BLOCKS  32                   // 512 elems each
#define GRID1       (MEL_BLOCKS + ATTN_BLOCKS + DUR_BLOCKS)   // 864 <= 888 @6/SM
#define NTHREADS    256

// ---- per-block partial slots (deterministic fixed-order combine) ----
__device__ float g_mel_partial[MEL_BLOCKS];
__device__ float g_post_partial[MEL_BLOCKS];
__device__ float g_attn_num[ATTN_BLOCKS];   // layout: b*10 + chunk
__device__ float g_attn_den[ATTN_BLOCKS];
__device__ float g_dur_partial[DUR_BLOCKS];
__device__ unsigned int g_counter = 0;      // arrival count; reset by finalize

__device__ __forceinline__ float block_reduce256(float v, float* sh) {
    int tid = threadIdx.x;
    #pragma unroll
    for (int o = 16; o > 0; o >>= 1) v += __shfl_down_sync(0xffffffffu, v, o);
    if ((tid & 31) == 0) sh[tid >> 5] = v;
    __syncthreads();
    float r = 0.0f;
    if (tid < 8) {
        r = sh[tid];
        #pragma unroll
        for (int o = 4; o > 0; o >>= 1) r += __shfl_down_sync(0xffu, r, o);
    }
    __syncthreads();
    return r;   // valid on tid 0
}

__global__ __launch_bounds__(NTHREADS)
void partials_kernel(const float* __restrict__ mel_t,
                     const float* __restrict__ mel_p,
                     const float* __restrict__ post_p,
                     const int*   __restrict__ mel_lens,
                     const float* __restrict__ attn,
                     const int*   __restrict__ x_len,
                     const int*   __restrict__ lip_len,
                     const float* __restrict__ logdur_p,
                     const int*   __restrict__ dur_t)
{
    __shared__ float sh[8];
    const int bid = blockIdx.x;
    const int tid = threadIdx.x;

    if (bid < MEL_BLOCKS) {
        // ---- tile: batch b, mel-rows [m0, m0+128) ----
        const int b   = bid >> 4;
        const int m0  = (bid & 15) << 7;
        const int len = mel_lens[b];
        float s1 = 0.0f, s2 = 0.0f;

        const size_t base = ((size_t)b * Mn + m0) * (NMEL / 4);
        const float4* __restrict__ t4 = reinterpret_cast<const float4*>(mel_t)  + base;
        const float4* __restrict__ p4 = reinterpret_cast<const float4*>(mel_p)  + base;
        const float4* __restrict__ q4 = reinterpret_cast<const float4*>(post_p) + base;

        if (m0 + 128 <= len) {
            #pragma unroll
            for (int u = 0; u < 10; u += 2) {
                const int i0 = u * NTHREADS + tid;
                const int i1 = i0 + NTHREADS;
                float4 ta = t4[i0], pa = p4[i0], qa = q4[i0];
                float4 tb = t4[i1], pb = p4[i1], qb = q4[i1];
                s1 += fabsf(pa.x - ta.x) + fabsf(pa.y - ta.y)
                    + fabsf(pa.z - ta.z) + fabsf(pa.w - ta.w);
                s2 += fabsf(qa.x - ta.x) + fabsf(qa.y - ta.y)
                    + fabsf(qa.z - ta.z) + fabsf(qa.w - ta.w);
                s1 += fabsf(pb.x - tb.x) + fabsf(pb.y - tb.y)
                    + fabsf(pb.z - tb.z) + fabsf(pb.w - tb.w);
                s2 += fabsf(qb.x - tb.x) + fabsf(qb.y - tb.y)
                    + fabsf(qb.z - tb.z) + fabsf(qb.w - tb.w);
            }
        } else if (m0 < len) {
            const int nv = (len - m0) * (NMEL / 4);
            for (int i = tid; i < nv; i += NTHREADS) {
                float4 ta = t4[i], pa = p4[i], qa = q4[i];
                s1 += fabsf(pa.x - ta.x) + fabsf(pa.y - ta.y)
                    + fabsf(pa.z - ta.z) + fabsf(pa.w - ta.w);
                s2 += fabsf(qa.x - ta.x) + fabsf(qa.y - ta.y)
                    + fabsf(qa.z - ta.z) + fabsf(qa.w - ta.w);
            }
        }
        float r1 = block_reduce256(s1, sh);
        float r2 = block_reduce256(s2, sh);
        if (tid == 0) { g_mel_partial[bid] = r1; g_post_partial[bid] = r2; }
    } else if (bid < MEL_BLOCKS + ATTN_BLOCKS) {
        // ---- attn tile: batch b, t-rows [t0, t0+52), lane owns 4 columns ----
        const int id = bid - MEL_BLOCKS;
        const int b  = id / ATTN_PER_B;
        const int c  = id % ATTN_PER_B;
        const int t0 = c * ATTN_ROWS;
        const int xl = x_len[b];
        const int ll = lip_len[b];
        const float ks = (float)ll / (float)xl;
        const float da = (float)ll * 0.125f;        // lip_len / DIAR(8)

        __shared__ float s_y1[ATTN_ROWS], s_y2[ATTN_ROWS];
        if (tid < ATTN_ROWS) {
            const float kt = __fmul_rn(ks, (float)(t0 + tid));
            s_y1[tid] = floorf(__fadd_rn(kt, da));
            s_y2[tid] = floorf(fmaxf(__fsub_rn(kt, da), 0.0f));
        }
        __syncthreads();

        float num = 0.0f, den = 0.0f;
        const int l0 = tid << 2;
        const int nt = min(min(t0 + ATTN_ROWS, Tn), xl) - t0;
        if (l0 < ll && nt > 0) {
            const float lf0 = (float)l0, lf1 = lf0 + 1.0f,
                        lf2 = lf0 + 2.0f, lf3 = lf0 + 3.0f;
            const bool v1 = (l0 + 1 < ll), v2 = (l0 + 2 < ll), v3 = (l0 + 3 < ll);
            const float4* __restrict__ a4 =
                reinterpret_cast<const float4*>(attn) +
                ((size_t)b * Tn + t0) * (Ln / 4) + tid;
            #pragma unroll 2
            for (int t = 0; t < nt; ++t) {
                float4 v = a4[(size_t)t * (Ln / 4)];
                const float y1 = s_y1[t], y2 = s_y2[t];
                den += v.x;
                if (lf0 >= y2 && lf0 < y1) num += v.x;
                if (v1) { den += v.y; if (lf1 >= y2 && lf1 < y1) num += v.y; }
                if (v2) { den += v.z; if (lf2 >= y2 && lf2 < y1) num += v.z; }
                if (v3) { den += v.w; if (lf3 >= y2 && lf3 < y1) num += v.w; }
            }
        }
        float rn = block_reduce256(num, sh);
        float rd = block_reduce256(den, sh);
        if (tid == 0) { g_attn_num[id] = rn; g_attn_den[id] = rd; }
    } else {
        // ---- duration MSE in log domain: 32 blocks x 512 elems ----
        const int id = bid - MEL_BLOCKS - ATTN_BLOCKS;  // 0..31
        float s = 0.0f;
        #pragma unroll
        for (int k = 0; k < 2; ++k) {
            const int idx = id * 512 + k * NTHREADS + tid;   // < B*T
            const int b = idx >> 9;          // / Tn
            const int t = idx & 511;         // % Tn
            if (t < x_len[b]) {
                float d = logdur_p[idx] - logf((float)dur_t[idx] + 1.0f);
                s += d * d;
            }
        }
        float r = block_reduce256(s, sh);
        if (tid == 0) g_dur_partial[id] = r;
    }

    // arrival: tid0 is the sole slot writer -> release just its own stores
    if (tid == 0) {
        __threadfence();
        atomicAdd(&g_counter, 1u);
    }
}

// ---- finalize: CONCURRENT kernel; spins on arrival counter ----
__global__ __launch_bounds__(NTHREADS)
void finalize_kernel(const int*   __restrict__ mel_lens,
                     const int*   __restrict__ x_len,
                     const float* __restrict__ spk_p,
                     const float* __restrict__ spk_e,
                     float* __restrict__ out)
{
    __shared__ float sh[8];
    __shared__ float resv[8];   // 0 spk, 1 cnt_rows, 2 xsum, 3 mel, 4 post, 5 dur, 6 focus
    const int tid  = threadIdx.x;
    const int warp = tid >> 5, lane = tid & 31;

    // ---------- independent work (overlaps with partials) ----------
    float spk_term = 0.0f;
    {
        float acc = 0.0f;
        #pragma unroll
        for (int i = 0; i < 4; ++i) {
            const int b = warp * 4 + i;
            float dot = 0.0f, n1 = 0.0f, n2 = 0.0f;
            #pragma unroll
            for (int e = 0; e < DSPK / 32; ++e) {
                const float p = spk_p[b * DSPK + lane + e * 32];
                const float q = spk_e[b * DSPK + lane + e * 32];
                dot += p * q; n1 += p * p; n2 += q * q;
            }
            #pragma unroll
            for (int o = 16; o > 0; o >>= 1) {
                dot += __shfl_down_sync(0xffffffffu, dot, o);
                n1  += __shfl_down_sync(0xffffffffu, n1, o);
                n2  += __shfl_down_sync(0xffffffffu, n2, o);
            }
            if (lane == 0) {
                const float eps = 1e-6f;
                acc += 1.0f - dot / (fmaxf(sqrtf(n1), eps) * fmaxf(sqrtf(n2), eps));
            }
        }
        spk_term = acc;
    }
    float cr = (tid < Bn) ? (float)mel_lens[tid] : 0.0f;
    float xr = (tid < Bn) ? (float)x_len[tid]    : 0.0f;

    float r;
    r = block_reduce256(spk_term, sh); if (tid == 0) resv[0] = r;
    r = block_reduce256(cr, sh);       if (tid == 0) resv[1] = r;
    r = block_reduce256(xr, sh);       if (tid == 0) resv[2] = r;

    // ---------- software sync: wait for all partials blocks ----------
    if (tid == 0) {
        unsigned long long iters = 0;
        while (true) {
            unsigned int v;
            asm volatile("ld.acquire.gpu.u32 %0, [%1];"
                         : "=r"(v) : "l"(&g_counter));
            if (v >= (unsigned int)GRID1) break;
            if (++iters > 100000000ull) break;   // bounded safety
        }
    }
    __syncthreads();
    __threadfence();    // acquire: slot stores now visible

    // ---------- slot reduction (L2-hot) ----------
    float vm = g_mel_partial[tid]  + g_mel_partial[tid + 256];
    float vp = g_post_partial[tid] + g_post_partial[tid + 256];
    float vd = (tid < DUR_BLOCKS) ? g_dur_partial[tid] : 0.0f;

    // focus: warp w handles batches 4w..4w+3; lanes 0..9 load that batch's chunks
    float fsum = 0.0f;
    #pragma unroll
    for (int i = 0; i < 4; ++i) {
        const int b = warp * 4 + i;
        float n = 0.0f, d = 0.0f;
        if (lane < ATTN_PER_B) {
            n = g_attn_num[b * ATTN_PER_B + lane];
            d = g_attn_den[b * ATTN_PER_B + lane];
        }
        #pragma unroll
        for (int o = 8; o > 0; o >>= 1) {
            n += __shfl_down_sync(0xffffffffu, n, o, 16);
            d += __shfl_down_sync(0xffffffffu, d, o, 16);
        }
        if (lane == 0) fsum += n / d;
    }

    r = block_reduce256(vm, sh);   if (tid == 0) resv[3] = r;
    r = block_reduce256(vp, sh);   if (tid == 0) resv[4] = r;
    r = block_reduce256(vd, sh);   if (tid == 0) resv[5] = r;
    r = block_reduce256(fsum, sh); if (tid == 0) resv[6] = r;
    __syncthreads();

    if (tid == 0) {
        const float cnt = resv[1] * (float)NMEL;
        const float mel_loss      = resv[3] / cnt;                 // MEL_LW = 1
        const float postnet_loss  = resv[4] / cnt;
        const float duration_loss = resv[5] / resv[2];             // DUR_W = 1
        const float speaker_loss  = resv[0] / (float)Bn;           // SPK_W = 1
        const float diagonal_loss = 0.1f * -logf(resv[6] / (float)Bn);
        const float total = mel_loss + postnet_loss + duration_loss
                          + speaker_loss + diagonal_loss;
        out[0] = total;
        out[1] = mel_loss;
        out[2] = postnet_loss;
        out[3] = speaker_loss;
        out[4] = duration_loss;
        out[5] = diagonal_loss;

        g_counter = 0;   // sole consumer resets for next replay
    }
}

extern "C" void kernel_launch(void* const* d_in, const int* in_sizes, int n_in,
                              void* d_out, int out_size)
{
    const float* mel_t    = (const float*)d_in[2];
    const int*   mel_lens = (const int*)  d_in[5];
    const int*   dur_t    = (const int*)  d_in[6];
    const float* mel_p    = (const float*)d_in[8];
    const float* post_p   = (const float*)d_in[9];
    const float* logdur_p = (const float*)d_in[10];
    const float* spk_p    = (const float*)d_in[14];
    const float* spk_e    = (const float*)d_in[15];
    const float* attn     = (const float*)d_in[16];
    const int*   x_len    = (const int*)  d_in[17];
    const int*   lip_len  = (const int*)  d_in[18];

    static cudaStream_t s2 = nullptr;
    static cudaEvent_t ev_fork = nullptr, ev_join = nullptr;
    if (s2 == nullptr) {
        cudaStreamCreateWithFlags(&s2, cudaStreamNonBlocking);
        cudaEventCreateWithFlags(&ev_fork, cudaEventDisableTiming);
        cudaEventCreateWithFlags(&ev_join, cudaEventDisableTiming);
    }

    // fork: finalize runs CONCURRENTLY with partials (R11 ordering)
    cudaEventRecord(ev_fork, 0);
    cudaStreamWaitEvent(s2, ev_fork, 0);

    partials_kernel<<<GRID1, NTHREADS>>>(
        mel_t, mel_p, post_p, mel_lens, attn, x_len, lip_len, logdur_p, dur_t);

    finalize_kernel<<<1, NTHREADS, 0, s2>>>(
        mel_lens, x_len, spk_p, spk_e, (float*)d_out);

    // join: graph completion includes finalize
    cudaEventRecord(ev_join, s2);
    cudaStreamWaitEvent(0, ev_join, 0);
}

// round 17
// speedup vs baseline: 1.3200x; 1.3200x over previous
#include <cuda_runtime.h>
#include <math.h>

#define Bn   32
#define Tn   512
#define Mn   2048
#define Ln   1024
#define NMEL 80
#define DSPK 256

#define MEL_BLOCKS  512                  // 16 per batch, 128 mel-rows each
#define ATTN_BLOCKS 512                  // 16 per batch, 32 t-rows each
#define DUR_BLOCKS  64
#define GRID1       (MEL_BLOCKS + ATTN_BLOCKS + DUR_BLOCKS)   // 1088
#define NTHREADS    256

// ---- per-block partial slots (deterministic fixed-order combine) ----
__device__ float g_mel_partial[MEL_BLOCKS];
__device__ float g_post_partial[MEL_BLOCKS];
__device__ float g_attn_num[ATTN_BLOCKS];   // layout: b*16 + chunk
__device__ float g_attn_den[ATTN_BLOCKS];
__device__ float g_dur_partial[DUR_BLOCKS];
__device__ unsigned int g_counter = 0;      // arrival count; reset by finalize

__device__ __forceinline__ float block_reduce256(float v, float* sh) {
    int tid = threadIdx.x;
    #pragma unroll
    for (int o = 16; o > 0; o >>= 1) v += __shfl_down_sync(0xffffffffu, v, o);
    if ((tid & 31) == 0) sh[tid >> 5] = v;
    __syncthreads();
    float r = 0.0f;
    if (tid < 8) {
        r = sh[tid];
        #pragma unroll
        for (int o = 4; o > 0; o >>= 1) r += __shfl_down_sync(0xffu, r, o);
    }
    __syncthreads();
    return r;   // valid on tid 0
}

__global__ __launch_bounds__(NTHREADS)
void partials_kernel(const float* __restrict__ mel_t,
                     const float* __restrict__ mel_p,
                     const float* __restrict__ post_p,
                     const int*   __restrict__ mel_lens,
                     const float* __restrict__ attn,
                     const int*   __restrict__ x_len,
                     const int*   __restrict__ lip_len,
                     const float* __restrict__ logdur_p,
                     const int*   __restrict__ dur_t)
{
    __shared__ float sh[8];
    const int bid = blockIdx.x;
    const int tid = threadIdx.x;

    if (bid < MEL_BLOCKS) {
        // ---- tile: batch b, mel-rows [m0, m0+128) ----
        const int b   = bid >> 4;
        const int m0  = (bid & 15) << 7;
        const int len = mel_lens[b];
        float s1 = 0.0f, s2 = 0.0f;

        const size_t base = ((size_t)b * Mn + m0) * (NMEL / 4);
        const float4* __restrict__ t4 = reinterpret_cast<const float4*>(mel_t)  + base;
        const float4* __restrict__ p4 = reinterpret_cast<const float4*>(mel_p)  + base;
        const float4* __restrict__ q4 = reinterpret_cast<const float4*>(post_p) + base;

        if (m0 + 128 <= len) {
            #pragma unroll
            for (int u = 0; u < 10; u += 2) {
                const int i0 = u * NTHREADS + tid;
                const int i1 = i0 + NTHREADS;
                float4 ta = t4[i0], pa = p4[i0], qa = q4[i0];
                float4 tb = t4[i1], pb = p4[i1], qb = q4[i1];
                s1 += fabsf(pa.x - ta.x) + fabsf(pa.y - ta.y)
                    + fabsf(pa.z - ta.z) + fabsf(pa.w - ta.w);
                s2 += fabsf(qa.x - ta.x) + fabsf(qa.y - ta.y)
                    + fabsf(qa.z - ta.z) + fabsf(qa.w - ta.w);
                s1 += fabsf(pb.x - tb.x) + fabsf(pb.y - tb.y)
                    + fabsf(pb.z - tb.z) + fabsf(pb.w - tb.w);
                s2 += fabsf(qb.x - tb.x) + fabsf(qb.y - tb.y)
                    + fabsf(qb.z - tb.z) + fabsf(qb.w - tb.w);
            }
        } else if (m0 < len) {
            const int nv = (len - m0) * (NMEL / 4);
            for (int i = tid; i < nv; i += NTHREADS) {
                float4 ta = t4[i], pa = p4[i], qa = q4[i];
                s1 += fabsf(pa.x - ta.x) + fabsf(pa.y - ta.y)
                    + fabsf(pa.z - ta.z) + fabsf(pa.w - ta.w);
                s2 += fabsf(qa.x - ta.x) + fabsf(qa.y - ta.y)
                    + fabsf(qa.z - ta.z) + fabsf(qa.w - ta.w);
            }
        }
        float r1 = block_reduce256(s1, sh);
        float r2 = block_reduce256(s2, sh);
        if (tid == 0) { g_mel_partial[bid] = r1; g_post_partial[bid] = r2; }
    } else if (bid < MEL_BLOCKS + ATTN_BLOCKS) {
        // ---- attn tile: batch b, t-rows [t0, t0+32), lane owns 4 columns ----
        const int id = bid - MEL_BLOCKS;
        const int b  = id >> 4;
        const int t0 = (id & 15) << 5;
        const int xl = x_len[b];
        const int ll = lip_len[b];
        const float ks = (float)ll / (float)xl;
        const float da = (float)ll * 0.125f;        // lip_len / DIAR(8)

        __shared__ float s_y1[32], s_y2[32];
        if (tid < 32) {
            const float kt = __fmul_rn(ks, (float)(t0 + tid));
            s_y1[tid] = floorf(__fadd_rn(kt, da));
            s_y2[tid] = floorf(fmaxf(__fsub_rn(kt, da), 0.0f));
        }
        __syncthreads();

        float num = 0.0f, den = 0.0f;
        const int l0 = tid << 2;
        const int nt = min(t0 + 32, xl) - t0;       // rows monotonically masked
        if (l0 < ll && nt > 0) {
            const float lf0 = (float)l0, lf1 = lf0 + 1.0f,
                        lf2 = lf0 + 2.0f, lf3 = lf0 + 3.0f;
            const bool v1 = (l0 + 1 < ll), v2 = (l0 + 2 < ll), v3 = (l0 + 3 < ll);
            const float4* __restrict__ a4 =
                reinterpret_cast<const float4*>(attn) +
                ((size_t)b * Tn + t0) * (Ln / 4) + tid;
            #pragma unroll 4
            for (int t = 0; t < nt; ++t) {
                float4 v = a4[(size_t)t * (Ln / 4)];
                const float y1 = s_y1[t], y2 = s_y2[t];
                den += v.x;
                if (lf0 >= y2 && lf0 < y1) num += v.x;
                if (v1) { den += v.y; if (lf1 >= y2 && lf1 < y1) num += v.y; }
                if (v2) { den += v.z; if (lf2 >= y2 && lf2 < y1) num += v.z; }
                if (v3) { den += v.w; if (lf3 >= y2 && lf3 < y1) num += v.w; }
            }
        }
        float rn = block_reduce256(num, sh);
        float rd = block_reduce256(den, sh);
        if (tid == 0) { g_attn_num[id] = rn; g_attn_den[id] = rd; }
    } else {
        // ---- duration MSE in log domain ----
        const int id  = bid - MEL_BLOCKS - ATTN_BLOCKS;  // 0..63
        const int idx = id * NTHREADS + tid;             // < B*T
        const int b = idx / Tn;
        const int t = idx % Tn;
        float s = 0.0f;
        if (t < x_len[b]) {
            float d = logdur_p[idx] - logf((float)dur_t[idx] + 1.0f);
            s = d * d;
        }
        float r = block_reduce256(s, sh);
        if (tid == 0) g_dur_partial[id] = r;
    }

    // arrival: tid0 is the sole slot writer -> release just its own stores
    if (tid == 0) {
        __threadfence();
        atomicAdd(&g_counter, 1u);
    }
}

// ---- finalize: CONCURRENT kernel; spins on arrival counter ----
__global__ __launch_bounds__(NTHREADS)
void finalize_kernel(const int*   __restrict__ mel_lens,
                     const int*   __restrict__ x_len,
                     const float* __restrict__ spk_p,
                     const float* __restrict__ spk_e,
                     float* __restrict__ out)
{
    __shared__ float sh[8];
    __shared__ float resv[8];   // 0 spk, 1 cnt_rows, 2 xsum, 3 mel, 4 post, 5 dur, 6 focus
    const int tid  = threadIdx.x;
    const int warp = tid >> 5, lane = tid & 31;

    // ---------- independent work (overlaps with partials) ----------
    float spk_term = 0.0f;
    {
        float acc = 0.0f;
        #pragma unroll
        for (int i = 0; i < 4; ++i) {
            const int b = warp * 4 + i;
            float dot = 0.0f, n1 = 0.0f, n2 = 0.0f;
            #pragma unroll
            for (int e = 0; e < DSPK / 32; ++e) {
                const float p = spk_p[b * DSPK + lane + e * 32];
                const float q = spk_e[b * DSPK + lane + e * 32];
                dot += p * q; n1 += p * p; n2 += q * q;
            }
            #pragma unroll
            for (int o = 16; o > 0; o >>= 1) {
                dot += __shfl_down_sync(0xffffffffu, dot, o);
                n1  += __shfl_down_sync(0xffffffffu, n1, o);
                n2  += __shfl_down_sync(0xffffffffu, n2, o);
            }
            if (lane == 0) {
                const float eps = 1e-6f;
                acc += 1.0f - dot / (fmaxf(sqrtf(n1), eps) * fmaxf(sqrtf(n2), eps));
            }
        }
        spk_term = acc;
    }
    float cr = (tid < Bn) ? (float)mel_lens[tid] : 0.0f;
    float xr = (tid < Bn) ? (float)x_len[tid]    : 0.0f;

    float r;
    r = block_reduce256(spk_term, sh); if (tid == 0) resv[0] = r;
    r = block_reduce256(cr, sh);       if (tid == 0) resv[1] = r;
    r = block_reduce256(xr, sh);       if (tid == 0) resv[2] = r;

    // ---------- software sync: wait for all partials blocks ----------
    if (tid == 0) {
        unsigned long long iters = 0;
        while (true) {
            unsigned int v;
            asm volatile("ld.acquire.gpu.u32 %0, [%1];"
                         : "=r"(v) : "l"(&g_counter));
            if (v >= (unsigned int)GRID1) break;
            if (++iters > 100000000ull) break;   // bounded safety
        }
    }
    __syncthreads();
    __threadfence();    // acquire: slot stores now visible

    // ---------- slot reduction (L2-hot) ----------
    float vm = g_mel_partial[tid]  + g_mel_partial[tid + 256];
    float vp = g_post_partial[tid] + g_post_partial[tid + 256];
    float vd = (tid < DUR_BLOCKS) ? g_dur_partial[tid] : 0.0f;

    // attn: 2 chunks per thread; 8-thread segment == one batch (16 chunks)
    float an = g_attn_num[2 * tid] + g_attn_num[2 * tid + 1];
    float ad = g_attn_den[2 * tid] + g_attn_den[2 * tid + 1];
    #pragma unroll
    for (int o = 4; o > 0; o >>= 1) {
        an += __shfl_down_sync(0xffffffffu, an, o, 8);
        ad += __shfl_down_sync(0xffffffffu, ad, o, 8);
    }
    float focus = ((tid & 7) == 0) ? an / ad : 0.0f;

    r = block_reduce256(vm, sh);    if (tid == 0) resv[3] = r;
    r = block_reduce256(vp, sh);    if (tid == 0) resv[4] = r;
    r = block_reduce256(vd, sh);    if (tid == 0) resv[5] = r;
    r = block_reduce256(focus, sh); if (tid == 0) resv[6] = r;
    __syncthreads();

    if (tid == 0) {
        const float cnt = resv[1] * (float)NMEL;
        const float mel_loss      = resv[3] / cnt;                 // MEL_LW = 1
        const float postnet_loss  = resv[4] / cnt;
        const float duration_loss = resv[5] / resv[2];             // DUR_W = 1
        const float speaker_loss  = resv[0] / (float)Bn;           // SPK_W = 1
        const float diagonal_loss = 0.1f * -logf(resv[6] / (float)Bn);
        const float total = mel_loss + postnet_loss + duration_loss
                          + speaker_loss + diagonal_loss;
        out[0] = total;
        out[1] = mel_loss;
        out[2] = postnet_loss;
        out[3] = speaker_loss;
        out[4] = duration_loss;
        out[5] = diagonal_loss;

        g_counter = 0;   // sole consumer resets for next replay
    }
}

extern "C" void kernel_launch(void* const* d_in, const int* in_sizes, int n_in,
                              void* d_out, int out_size)
{
    const float* mel_t    = (const float*)d_in[2];
    const int*   mel_lens = (const int*)  d_in[5];
    const int*   dur_t    = (const int*)  d_in[6];
    const float* mel_p    = (const float*)d_in[8];
    const float* post_p   = (const float*)d_in[9];
    const float* logdur_p = (const float*)d_in[10];
    const float* spk_p    = (const float*)d_in[14];
    const float* spk_e    = (const float*)d_in[15];
    const float* attn     = (const float*)d_in[16];
    const int*   x_len    = (const int*)  d_in[17];
    const int*   lip_len  = (const int*)  d_in[18];

    static cudaStream_t s2 = nullptr;
    static cudaEvent_t ev_fork = nullptr, ev_join = nullptr;
    if (s2 == nullptr) {
        cudaStreamCreateWithFlags(&s2, cudaStreamNonBlocking);
        cudaEventCreateWithFlags(&ev_fork, cudaEventDisableTiming);
        cudaEventCreateWithFlags(&ev_join, cudaEventDisableTiming);
    }

    // fork: finalize runs CONCURRENTLY with partials (R11 ordering)
    cudaEventRecord(ev_fork, 0);
    cudaStreamWaitEvent(s2, ev_fork, 0);

    partials_kernel<<<GRID1, NTHREADS>>>(
        mel_t, mel_p, post_p, mel_lens, attn, x_len, lip_len, logdur_p, dur_t);

    finalize_kernel<<<1, NTHREADS, 0, s2>>>(
        mel_lens, x_len, spk_p, spk_e, (float*)d_out);

    // join: graph completion includes finalize
    cudaEventRecord(ev_join, s2);
    cudaStreamWaitEvent(0, ev_join, 0);
}